// round 5
// baseline (speedup 1.0000x reference)
#include <cuda_runtime.h>

#define NN   50000
#define NE   50000
#define NNZT 800000
#define INC  512
#define HIDC 256
#define OUTC 64

// ---------------- scratch (static device globals; no allocs allowed) ----------
__device__ float g_h1[NN * HIDC];   // x@W1, later reused for relu(conv1) output
__device__ float g_m1[NE * HIDC];   // hyperedge features, conv1
__device__ float g_h2[NN * OUTC];   // h@W2
__device__ float g_m2[NE * OUTC];   // hyperedge features, conv2
__device__ int   g_degN[NN];
__device__ int   g_degE[NE];
__device__ int   g_rpN[NN + 1];
__device__ int   g_rpE[NE + 1];
__device__ int   g_curN[NN];
__device__ int   g_curE[NE];
__device__ int   g_adjE[NNZT];      // node ids grouped by hyperedge
__device__ int   g_adjN[NNZT];      // hyperedge ids grouped by node
__device__ int   g_is64;            // 1 if edge_index buffer is int64, 0 if int32

// ---------------- dtype detection -------------------------------------------
// int64 non-negative values < 2^31 (little-endian): every odd int32 word is 0.
// Genuine int32 indices: odd words are random in [0, 50000) -> ~never all zero.
__global__ void detect_dtype(const int* __restrict__ ei32) {
    __shared__ int any_nonzero;
    if (threadIdx.x == 0) any_nonzero = 0;
    __syncthreads();
    int t = threadIdx.x;
    for (int j = t; j < 1024; j += blockDim.x) {
        if (ei32[2 * j + 1] != 0) atomicOr(&any_nonzero, 1);
    }
    __syncthreads();
    if (threadIdx.x == 0) g_is64 = any_nonzero ? 0 : 1;
}

__device__ __forceinline__ void load_pair(const int* __restrict__ ei32, int i,
                                          int& v, int& e) {
    if (g_is64) {
        v = ei32[2 * (size_t)i];
        e = ei32[2 * ((size_t)NNZT + i)];
    } else {
        v = ei32[i];
        e = ei32[NNZT + i];
    }
}

// ---------------- CSR build ---------------------------------------------------
__global__ void zero_counts() {
    int i = blockIdx.x * blockDim.x + threadIdx.x;
    if (i < NN) { g_degN[i] = 0; g_curN[i] = 0; }
    if (i < NE) { g_degE[i] = 0; g_curE[i] = 0; }
}

__global__ void count_deg(const int* __restrict__ ei32) {
    int i = blockIdx.x * blockDim.x + threadIdx.x;
    if (i >= NNZT) return;
    int v, e;
    load_pair(ei32, i, v, e);
    if ((unsigned)v >= NN || (unsigned)e >= NE) return;  // safety net
    atomicAdd(&g_degN[v], 1);
    atomicAdd(&g_degE[e], 1);
}

// exclusive scan of n (<=50000) ints, single block of 1024 threads
__global__ void scan_excl(const int* __restrict__ deg, int* __restrict__ rp, int n) {
    __shared__ int sh[1024];
    __shared__ int soff;
    int t = threadIdx.x;
    if (t == 0) soff = 0;
    __syncthreads();
    for (int base = 0; base < n; base += 1024) {
        int i = base + t;
        int v = (i < n) ? deg[i] : 0;
        sh[t] = v;
        __syncthreads();
        for (int d = 1; d < 1024; d <<= 1) {
            int add = (t >= d) ? sh[t - d] : 0;
            __syncthreads();
            sh[t] += add;
            __syncthreads();
        }
        if (i < n) rp[i] = soff + sh[t] - v;
        int tot = sh[1023];
        __syncthreads();
        if (t == 0) soff += tot;
        __syncthreads();
    }
    if (t == 0) rp[n] = soff;
}

__global__ void fill_adj(const int* __restrict__ ei32) {
    int i = blockIdx.x * blockDim.x + threadIdx.x;
    if (i >= NNZT) return;
    int v, e;
    load_pair(ei32, i, v, e);
    if ((unsigned)v >= NN || (unsigned)e >= NE) return;  // safety net
    int p = atomicAdd(&g_curE[e], 1);
    g_adjE[g_rpE[e] + p] = v;
    int q = atomicAdd(&g_curN[v], 1);
    g_adjN[g_rpN[v] + q] = e;
}

// ---------------- tiled SGEMM: C[M,N] = A[M,K] @ B[K,N] -----------------------
template <int BM, int BN, int BK, int TM, int TN>
__global__ void sgemm_k(const float* __restrict__ A, const float* __restrict__ B,
                        float* __restrict__ C, int M, int N, int K) {
    constexpr int NT = (BM / TM) * (BN / TN);
    __shared__ float As[BK][BM];
    __shared__ float Bs[BK][BN];
    const int tid  = threadIdx.x;
    const int tx   = tid % (BN / TN);
    const int ty   = tid / (BN / TN);
    const int row0 = blockIdx.x * BM;
    const int col0 = blockIdx.y * BN;

    float acc[TM][TN] = {};

    for (int k0 = 0; k0 < K; k0 += BK) {
        for (int idx = tid; idx < BM * BK / 4; idx += NT) {
            int m  = idx / (BK / 4);
            int kq = idx % (BK / 4);
            float4 a = make_float4(0.f, 0.f, 0.f, 0.f);
            if (row0 + m < M)
                a = *(const float4*)&A[(size_t)(row0 + m) * K + k0 + kq * 4];
            As[kq * 4 + 0][m] = a.x;
            As[kq * 4 + 1][m] = a.y;
            As[kq * 4 + 2][m] = a.z;
            As[kq * 4 + 3][m] = a.w;
        }
        for (int idx = tid; idx < BK * BN / 4; idx += NT) {
            int k  = idx / (BN / 4);
            int nq = idx % (BN / 4);
            *(float4*)&Bs[k][nq * 4] =
                *(const float4*)&B[(size_t)(k0 + k) * N + col0 + nq * 4];
        }
        __syncthreads();

#pragma unroll
        for (int k = 0; k < BK; k++) {
            float ra[TM], rb[TN];
#pragma unroll
            for (int i = 0; i < TM; i++) ra[i] = As[k][ty * TM + i];
#pragma unroll
            for (int j = 0; j < TN; j++) rb[j] = Bs[k][tx * TN + j];
#pragma unroll
            for (int i = 0; i < TM; i++)
#pragma unroll
                for (int j = 0; j < TN; j++) acc[i][j] += ra[i] * rb[j];
        }
        __syncthreads();
    }

#pragma unroll
    for (int i = 0; i < TM; i++) {
        int m = row0 + ty * TM + i;
        if (m < M) {
#pragma unroll
            for (int j = 0; j < TN; j += 4) {
                float4 v = make_float4(acc[i][j], acc[i][j + 1], acc[i][j + 2], acc[i][j + 3]);
                *(float4*)&C[(size_t)m * N + col0 + tx * TN + j] = v;
            }
        }
    }
}

// ---------------- gather-based segment mean (+bias, +relu) --------------------
// F4 float4 lanes per segment row; dst[seg] = (1/deg) * sum_{r in adj[seg]} src[r]
template <int F4, bool RELU, bool BIAS>
__global__ void agg_k(const float4* __restrict__ src, const int* __restrict__ rp,
                      const int* __restrict__ adj, const float* __restrict__ bias,
                      float4* __restrict__ dst, int nseg) {
    const int spb  = blockDim.x / F4;
    const int seg  = blockIdx.x * spb + threadIdx.x / F4;
    const int lane = threadIdx.x % F4;
    if (seg >= nseg) return;
    int s = rp[seg], e = rp[seg + 1];
    float4 acc = make_float4(0.f, 0.f, 0.f, 0.f);
    for (int j = s; j < e; j++) {
        int r    = __ldg(&adj[j]);
        float4 v = src[(size_t)r * F4 + lane];
        acc.x += v.x; acc.y += v.y; acc.z += v.z; acc.w += v.w;
    }
    float inv = (e > s) ? 1.0f / (float)(e - s) : 0.0f;
    acc.x *= inv; acc.y *= inv; acc.z *= inv; acc.w *= inv;
    if (BIAS) {
        float4 b = ((const float4*)bias)[lane];
        acc.x += b.x; acc.y += b.y; acc.z += b.z; acc.w += b.w;
    }
    if (RELU) {
        acc.x = fmaxf(acc.x, 0.f); acc.y = fmaxf(acc.y, 0.f);
        acc.z = fmaxf(acc.z, 0.f); acc.w = fmaxf(acc.w, 0.f);
    }
    dst[(size_t)seg * F4 + lane] = acc;
}

// ---------------- in-place log_softmax over 64 channels (warp per row) --------
__global__ void logsm64(float* __restrict__ d, int n) {
    int row  = blockIdx.x * (blockDim.x / 32) + threadIdx.x / 32;
    int lane = threadIdx.x & 31;
    if (row >= n) return;
    float2 v = *(float2*)&d[(size_t)row * 64 + lane * 2];
    float mx = fmaxf(v.x, v.y);
#pragma unroll
    for (int o = 16; o > 0; o >>= 1) mx = fmaxf(mx, __shfl_xor_sync(0xffffffffu, mx, o));
    float s = __expf(v.x - mx) + __expf(v.y - mx);
#pragma unroll
    for (int o = 16; o > 0; o >>= 1) s += __shfl_xor_sync(0xffffffffu, s, o);
    float l = mx + __logf(s);
    v.x -= l; v.y -= l;
    *(float2*)&d[(size_t)row * 64 + lane * 2] = v;
}

// ---------------- launch ------------------------------------------------------
extern "C" void kernel_launch(void* const* d_in, const int* in_sizes, int n_in,
                              void* d_out, int out_size) {
    const float* x   = (const float*)d_in[0];
    const int*   ei  = (const int*)d_in[1];     // int32 view; dtype auto-detected
    const float* W1  = (const float*)d_in[2];
    const float* b1  = (const float*)d_in[3];
    const float* W2  = (const float*)d_in[4];
    const float* b2  = (const float*)d_in[5];
    float*       out = (float*)d_out;

    float *h1, *m1, *h2, *m2;
    int *degN, *degE, *rpN, *rpE, *adjE, *adjN;
    cudaGetSymbolAddress((void**)&h1,   g_h1);
    cudaGetSymbolAddress((void**)&m1,   g_m1);
    cudaGetSymbolAddress((void**)&h2,   g_h2);
    cudaGetSymbolAddress((void**)&m2,   g_m2);
    cudaGetSymbolAddress((void**)&degN, g_degN);
    cudaGetSymbolAddress((void**)&degE, g_degE);
    cudaGetSymbolAddress((void**)&rpN,  g_rpN);
    cudaGetSymbolAddress((void**)&rpE,  g_rpE);
    cudaGetSymbolAddress((void**)&adjE, g_adjE);
    cudaGetSymbolAddress((void**)&adjN, g_adjN);

    // dtype detect + CSR build
    detect_dtype<<<1, 256>>>(ei);
    zero_counts<<<(NN + 255) / 256, 256>>>();
    count_deg<<<(NNZT + 255) / 256, 256>>>(ei);
    scan_excl<<<1, 1024>>>(degN, rpN, NN);
    scan_excl<<<1, 1024>>>(degE, rpE, NE);
    fill_adj<<<(NNZT + 255) / 256, 256>>>(ei);

    // conv1: h1 = x @ W1
    sgemm_k<128, 128, 8, 8, 8>
        <<<dim3((NN + 127) / 128, HIDC / 128), 256>>>(x, W1, h1, NN, HIDC, INC);
    // node -> hyperedge (mean), conv1
    agg_k<HIDC / 4, false, false>
        <<<(NE * (HIDC / 4) + 255) / 256, 256>>>((const float4*)h1, rpE, adjE, nullptr,
                                                 (float4*)m1, NE);
    // hyperedge -> node (mean) + b1 + relu, conv1 (writes back into h1)
    agg_k<HIDC / 4, true, true>
        <<<(NN * (HIDC / 4) + 255) / 256, 256>>>((const float4*)m1, rpN, adjN, b1,
                                                 (float4*)h1, NN);

    // conv2: h2 = h1 @ W2
    sgemm_k<128, 64, 8, 8, 4>
        <<<dim3((NN + 127) / 128, OUTC / 64), 256>>>(h1, W2, h2, NN, OUTC, HIDC);
    // node -> hyperedge (mean), conv2
    agg_k<OUTC / 4, false, false>
        <<<(NE * (OUTC / 4) + 255) / 256, 256>>>((const float4*)h2, rpE, adjE, nullptr,
                                                 (float4*)m2, NE);
    // hyperedge -> node (mean) + b2, conv2 -> d_out
    agg_k<OUTC / 4, false, true>
        <<<(NN * (OUTC / 4) + 255) / 256, 256>>>((const float4*)m2, rpN, adjN, b2,
                                                 (float4*)out, NN);

    // log_softmax in place
    logsm64<<<(NN + 7) / 8, 256>>>(out, NN);
}

// round 6
// speedup vs baseline: 1.0018x; 1.0018x over previous
#include <cuda_runtime.h>

#define NN   50000
#define NE   50000
#define NNZT 800000
#define INC  512
#define HIDC 256
#define OUTC 64

// ---------------- scratch (static device globals; no allocs allowed) ----------
__device__ float g_h1[NN * HIDC];   // x@W1, later reused for relu(conv1) output
__device__ float g_m1[NE * HIDC];   // hyperedge features, conv1
__device__ float g_h2[NN * OUTC];   // h@W2
__device__ float g_m2[NE * OUTC];   // hyperedge features, conv2
__device__ int   g_degN[NN];
__device__ int   g_degE[NE];
__device__ int   g_rpN[NN + 1];
__device__ int   g_rpE[NE + 1];
__device__ int   g_curN[NN];
__device__ int   g_curE[NE];
__device__ int   g_adjE[NNZT];      // node ids grouped by hyperedge
__device__ int   g_adjN[NNZT];      // hyperedge ids grouped by node
__device__ int   g_is64;            // 1 if edge_index buffer is int64, 0 if int32

// ---------------- dtype detection -------------------------------------------
// int64 non-negative values < 2^31 (little-endian): every odd int32 word is 0.
// Genuine int32 indices: odd words are random in [0, 50000) -> ~never all zero.
__global__ void detect_dtype(const int* __restrict__ ei32) {
    __shared__ int any_nonzero;
    if (threadIdx.x == 0) any_nonzero = 0;
    __syncthreads();
    int t = threadIdx.x;
    for (int j = t; j < 1024; j += blockDim.x) {
        if (ei32[2 * j + 1] != 0) atomicOr(&any_nonzero, 1);
    }
    __syncthreads();
    if (threadIdx.x == 0) g_is64 = any_nonzero ? 0 : 1;
}

__device__ __forceinline__ void load_pair(const int* __restrict__ ei32, int i,
                                          int& v, int& e) {
    if (g_is64) {
        v = ei32[2 * (size_t)i];
        e = ei32[2 * ((size_t)NNZT + i)];
    } else {
        v = ei32[i];
        e = ei32[NNZT + i];
    }
}

// ---------------- CSR build ---------------------------------------------------
__global__ void zero_counts() {
    int i = blockIdx.x * blockDim.x + threadIdx.x;
    if (i < NN) { g_degN[i] = 0; g_curN[i] = 0; }
    if (i < NE) { g_degE[i] = 0; g_curE[i] = 0; }
}

__global__ void count_deg(const int* __restrict__ ei32) {
    int i = blockIdx.x * blockDim.x + threadIdx.x;
    if (i >= NNZT) return;
    int v, e;
    load_pair(ei32, i, v, e);
    if ((unsigned)v >= NN || (unsigned)e >= NE) return;  // safety net
    atomicAdd(&g_degN[v], 1);
    atomicAdd(&g_degE[e], 1);
}

// exclusive scan of n (<=50000) ints, single block of 1024 threads
__global__ void scan_excl(const int* __restrict__ deg, int* __restrict__ rp, int n) {
    __shared__ int sh[1024];
    __shared__ int soff;
    int t = threadIdx.x;
    if (t == 0) soff = 0;
    __syncthreads();
    for (int base = 0; base < n; base += 1024) {
        int i = base + t;
        int v = (i < n) ? deg[i] : 0;
        sh[t] = v;
        __syncthreads();
        for (int d = 1; d < 1024; d <<= 1) {
            int add = (t >= d) ? sh[t - d] : 0;
            __syncthreads();
            sh[t] += add;
            __syncthreads();
        }
        if (i < n) rp[i] = soff + sh[t] - v;
        int tot = sh[1023];
        __syncthreads();
        if (t == 0) soff += tot;
        __syncthreads();
    }
    if (t == 0) rp[n] = soff;
}

__global__ void fill_adj(const int* __restrict__ ei32) {
    int i = blockIdx.x * blockDim.x + threadIdx.x;
    if (i >= NNZT) return;
    int v, e;
    load_pair(ei32, i, v, e);
    if ((unsigned)v >= NN || (unsigned)e >= NE) return;  // safety net
    int p = atomicAdd(&g_curE[e], 1);
    g_adjE[g_rpE[e] + p] = v;
    int q = atomicAdd(&g_curN[v], 1);
    g_adjN[g_rpN[v] + q] = e;
}

// ---------------- tiled SGEMM: C[M,N] = A[M,K] @ B[K,N] -----------------------
template <int BM, int BN, int BK, int TM, int TN>
__global__ void sgemm_k(const float* __restrict__ A, const float* __restrict__ B,
                        float* __restrict__ C, int M, int N, int K) {
    constexpr int NT = (BM / TM) * (BN / TN);
    __shared__ float As[BK][BM];
    __shared__ float Bs[BK][BN];
    const int tid  = threadIdx.x;
    const int tx   = tid % (BN / TN);
    const int ty   = tid / (BN / TN);
    const int row0 = blockIdx.x * BM;
    const int col0 = blockIdx.y * BN;

    float acc[TM][TN] = {};

    for (int k0 = 0; k0 < K; k0 += BK) {
        for (int idx = tid; idx < BM * BK / 4; idx += NT) {
            int m  = idx / (BK / 4);
            int kq = idx % (BK / 4);
            float4 a = make_float4(0.f, 0.f, 0.f, 0.f);
            if (row0 + m < M)
                a = *(const float4*)&A[(size_t)(row0 + m) * K + k0 + kq * 4];
            As[kq * 4 + 0][m] = a.x;
            As[kq * 4 + 1][m] = a.y;
            As[kq * 4 + 2][m] = a.z;
            As[kq * 4 + 3][m] = a.w;
        }
        for (int idx = tid; idx < BK * BN / 4; idx += NT) {
            int k  = idx / (BN / 4);
            int nq = idx % (BN / 4);
            *(float4*)&Bs[k][nq * 4] =
                *(const float4*)&B[(size_t)(k0 + k) * N + col0 + nq * 4];
        }
        __syncthreads();

#pragma unroll
        for (int k = 0; k < BK; k++) {
            float ra[TM], rb[TN];
#pragma unroll
            for (int i = 0; i < TM; i++) ra[i] = As[k][ty * TM + i];
#pragma unroll
            for (int j = 0; j < TN; j++) rb[j] = Bs[k][tx * TN + j];
#pragma unroll
            for (int i = 0; i < TM; i++)
#pragma unroll
                for (int j = 0; j < TN; j++) acc[i][j] += ra[i] * rb[j];
        }
        __syncthreads();
    }

#pragma unroll
    for (int i = 0; i < TM; i++) {
        int m = row0 + ty * TM + i;
        if (m < M) {
#pragma unroll
            for (int j = 0; j < TN; j += 4) {
                float4 v = make_float4(acc[i][j], acc[i][j + 1], acc[i][j + 2], acc[i][j + 3]);
                *(float4*)&C[(size_t)m * N + col0 + tx * TN + j] = v;
            }
        }
    }
}

// ---------------- gather-based segment mean (+bias, +relu) --------------------
// F4 float4 lanes per segment row; dst[seg] = (1/deg) * sum_{r in adj[seg]} src[r]
template <int F4, bool RELU, bool BIAS>
__global__ void agg_k(const float4* __restrict__ src, const int* __restrict__ rp,
                      const int* __restrict__ adj, const float* __restrict__ bias,
                      float4* __restrict__ dst, int nseg) {
    const int spb  = blockDim.x / F4;
    const int seg  = blockIdx.x * spb + threadIdx.x / F4;
    const int lane = threadIdx.x % F4;
    if (seg >= nseg) return;
    int s = rp[seg], e = rp[seg + 1];
    float4 acc = make_float4(0.f, 0.f, 0.f, 0.f);
    for (int j = s; j < e; j++) {
        int r    = __ldg(&adj[j]);
        float4 v = src[(size_t)r * F4 + lane];
        acc.x += v.x; acc.y += v.y; acc.z += v.z; acc.w += v.w;
    }
    float inv = (e > s) ? 1.0f / (float)(e - s) : 0.0f;
    acc.x *= inv; acc.y *= inv; acc.z *= inv; acc.w *= inv;
    if (BIAS) {
        float4 b = ((const float4*)bias)[lane];
        acc.x += b.x; acc.y += b.y; acc.z += b.z; acc.w += b.w;
    }
    if (RELU) {
        acc.x = fmaxf(acc.x, 0.f); acc.y = fmaxf(acc.y, 0.f);
        acc.z = fmaxf(acc.z, 0.f); acc.w = fmaxf(acc.w, 0.f);
    }
    dst[(size_t)seg * F4 + lane] = acc;
}

// ---------------- in-place log_softmax over 64 channels (warp per row) --------
__global__ void logsm64(float* __restrict__ d, int n) {
    int row  = blockIdx.x * (blockDim.x / 32) + threadIdx.x / 32;
    int lane = threadIdx.x & 31;
    if (row >= n) return;
    float2 v = *(float2*)&d[(size_t)row * 64 + lane * 2];
    float mx = fmaxf(v.x, v.y);
#pragma unroll
    for (int o = 16; o > 0; o >>= 1) mx = fmaxf(mx, __shfl_xor_sync(0xffffffffu, mx, o));
    float s = __expf(v.x - mx) + __expf(v.y - mx);
#pragma unroll
    for (int o = 16; o > 0; o >>= 1) s += __shfl_xor_sync(0xffffffffu, s, o);
    float l = mx + __logf(s);
    v.x -= l; v.y -= l;
    *(float2*)&d[(size_t)row * 64 + lane * 2] = v;
}

// ---------------- launch ------------------------------------------------------
extern "C" void kernel_launch(void* const* d_in, const int* in_sizes, int n_in,
                              void* d_out, int out_size) {
    const float* x   = (const float*)d_in[0];
    const int*   ei  = (const int*)d_in[1];     // int32 view; dtype auto-detected
    const float* W1  = (const float*)d_in[2];
    const float* b1  = (const float*)d_in[3];
    const float* W2  = (const float*)d_in[4];
    const float* b2  = (const float*)d_in[5];
    float*       out = (float*)d_out;

    float *h1, *m1, *h2, *m2;
    int *degN, *degE, *rpN, *rpE, *adjE, *adjN;
    cudaGetSymbolAddress((void**)&h1,   g_h1);
    cudaGetSymbolAddress((void**)&m1,   g_m1);
    cudaGetSymbolAddress((void**)&h2,   g_h2);
    cudaGetSymbolAddress((void**)&m2,   g_m2);
    cudaGetSymbolAddress((void**)&degN, g_degN);
    cudaGetSymbolAddress((void**)&degE, g_degE);
    cudaGetSymbolAddress((void**)&rpN,  g_rpN);
    cudaGetSymbolAddress((void**)&rpE,  g_rpE);
    cudaGetSymbolAddress((void**)&adjE, g_adjE);
    cudaGetSymbolAddress((void**)&adjN, g_adjN);

    // dtype detect + CSR build
    detect_dtype<<<1, 256>>>(ei);
    zero_counts<<<(NN + 255) / 256, 256>>>();
    count_deg<<<(NNZT + 255) / 256, 256>>>(ei);
    scan_excl<<<1, 1024>>>(degN, rpN, NN);
    scan_excl<<<1, 1024>>>(degE, rpE, NE);
    fill_adj<<<(NNZT + 255) / 256, 256>>>(ei);

    // conv1: h1 = x @ W1
    sgemm_k<128, 128, 8, 8, 8>
        <<<dim3((NN + 127) / 128, HIDC / 128), 256>>>(x, W1, h1, NN, HIDC, INC);
    // node -> hyperedge (mean), conv1
    agg_k<HIDC / 4, false, false>
        <<<(NE * (HIDC / 4) + 255) / 256, 256>>>((const float4*)h1, rpE, adjE, nullptr,
                                                 (float4*)m1, NE);
    // hyperedge -> node (mean) + b1 + relu, conv1 (writes back into h1)
    agg_k<HIDC / 4, true, true>
        <<<(NN * (HIDC / 4) + 255) / 256, 256>>>((const float4*)m1, rpN, adjN, b1,
                                                 (float4*)h1, NN);

    // conv2: h2 = h1 @ W2
    sgemm_k<128, 64, 8, 8, 4>
        <<<dim3((NN + 127) / 128, OUTC / 64), 256>>>(h1, W2, h2, NN, OUTC, HIDC);
    // node -> hyperedge (mean), conv2
    agg_k<OUTC / 4, false, false>
        <<<(NE * (OUTC / 4) + 255) / 256, 256>>>((const float4*)h2, rpE, adjE, nullptr,
                                                 (float4*)m2, NE);
    // hyperedge -> node (mean) + b2, conv2 -> d_out
    agg_k<OUTC / 4, false, true>
        <<<(NN * (OUTC / 4) + 255) / 256, 256>>>((const float4*)m2, rpN, adjN, b2,
                                                 (float4*)out, NN);

    // log_softmax in place
    logsm64<<<(NN + 7) / 8, 256>>>(out, NN);
}

// round 7
// speedup vs baseline: 1.0018x; 1.0000x over previous
#include <cuda_runtime.h>

#define NN   50000
#define NE   50000
#define NNZT 800000
#define INC  512
#define HIDC 256
#define OUTC 64

// ---------------- scratch (static device globals; no allocs allowed) ----------
__device__ float g_h1[NN * HIDC];   // x@W1, later reused for relu(conv1) output
__device__ float g_m1[NE * HIDC];   // hyperedge features, conv1
__device__ float g_h2[NN * OUTC];   // h@W2
__device__ float g_m2[NE * OUTC];   // hyperedge features, conv2
__device__ int   g_degN[NN];
__device__ int   g_degE[NE];
__device__ int   g_rpN[NN + 1];
__device__ int   g_rpE[NE + 1];
__device__ int   g_curN[NN];
__device__ int   g_curE[NE];
__device__ int   g_adjE[NNZT];      // node ids grouped by hyperedge
__device__ int   g_adjN[NNZT];      // hyperedge ids grouped by node
__device__ int   g_is64;            // 1 if edge_index buffer is int64, 0 if int32

// ---------------- dtype detection -------------------------------------------
// int64 non-negative values < 2^31 (little-endian): every odd int32 word is 0.
// Genuine int32 indices: odd words are random in [0, 50000) -> ~never all zero.
__global__ void detect_dtype(const int* __restrict__ ei32) {
    __shared__ int any_nonzero;
    if (threadIdx.x == 0) any_nonzero = 0;
    __syncthreads();
    int t = threadIdx.x;
    for (int j = t; j < 1024; j += blockDim.x) {
        if (ei32[2 * j + 1] != 0) atomicOr(&any_nonzero, 1);
    }
    __syncthreads();
    if (threadIdx.x == 0) g_is64 = any_nonzero ? 0 : 1;
}

__device__ __forceinline__ void load_pair(const int* __restrict__ ei32, int i,
                                          int& v, int& e) {
    if (g_is64) {
        v = ei32[2 * (size_t)i];
        e = ei32[2 * ((size_t)NNZT + i)];
    } else {
        v = ei32[i];
        e = ei32[NNZT + i];
    }
}

// ---------------- CSR build ---------------------------------------------------
__global__ void zero_counts() {
    int i = blockIdx.x * blockDim.x + threadIdx.x;
    if (i < NN) { g_degN[i] = 0; g_curN[i] = 0; }
    if (i < NE) { g_degE[i] = 0; g_curE[i] = 0; }
}

__global__ void count_deg(const int* __restrict__ ei32) {
    int i = blockIdx.x * blockDim.x + threadIdx.x;
    if (i >= NNZT) return;
    int v, e;
    load_pair(ei32, i, v, e);
    if ((unsigned)v >= NN || (unsigned)e >= NE) return;  // safety net
    atomicAdd(&g_degN[v], 1);
    atomicAdd(&g_degE[e], 1);
}

// exclusive scan of n (<=50000) ints, single block of 1024 threads
__global__ void scan_excl(const int* __restrict__ deg, int* __restrict__ rp, int n) {
    __shared__ int sh[1024];
    __shared__ int soff;
    int t = threadIdx.x;
    if (t == 0) soff = 0;
    __syncthreads();
    for (int base = 0; base < n; base += 1024) {
        int i = base + t;
        int v = (i < n) ? deg[i] : 0;
        sh[t] = v;
        __syncthreads();
        for (int d = 1; d < 1024; d <<= 1) {
            int add = (t >= d) ? sh[t - d] : 0;
            __syncthreads();
            sh[t] += add;
            __syncthreads();
        }
        if (i < n) rp[i] = soff + sh[t] - v;
        int tot = sh[1023];
        __syncthreads();
        if (t == 0) soff += tot;
        __syncthreads();
    }
    if (t == 0) rp[n] = soff;
}

__global__ void fill_adj(const int* __restrict__ ei32) {
    int i = blockIdx.x * blockDim.x + threadIdx.x;
    if (i >= NNZT) return;
    int v, e;
    load_pair(ei32, i, v, e);
    if ((unsigned)v >= NN || (unsigned)e >= NE) return;  // safety net
    int p = atomicAdd(&g_curE[e], 1);
    g_adjE[g_rpE[e] + p] = v;
    int q = atomicAdd(&g_curN[v], 1);
    g_adjN[g_rpN[v] + q] = e;
}

// ---------------- tiled SGEMM: C[M,N] = A[M,K] @ B[K,N] -----------------------
template <int BM, int BN, int BK, int TM, int TN>
__global__ void sgemm_k(const float* __restrict__ A, const float* __restrict__ B,
                        float* __restrict__ C, int M, int N, int K) {
    constexpr int NT = (BM / TM) * (BN / TN);
    __shared__ float As[BK][BM];
    __shared__ float Bs[BK][BN];
    const int tid  = threadIdx.x;
    const int tx   = tid % (BN / TN);
    const int ty   = tid / (BN / TN);
    const int row0 = blockIdx.x * BM;
    const int col0 = blockIdx.y * BN;

    float acc[TM][TN] = {};

    for (int k0 = 0; k0 < K; k0 += BK) {
        for (int idx = tid; idx < BM * BK / 4; idx += NT) {
            int m  = idx / (BK / 4);
            int kq = idx % (BK / 4);
            float4 a = make_float4(0.f, 0.f, 0.f, 0.f);
            if (row0 + m < M)
                a = *(const float4*)&A[(size_t)(row0 + m) * K + k0 + kq * 4];
            As[kq * 4 + 0][m] = a.x;
            As[kq * 4 + 1][m] = a.y;
            As[kq * 4 + 2][m] = a.z;
            As[kq * 4 + 3][m] = a.w;
        }
        for (int idx = tid; idx < BK * BN / 4; idx += NT) {
            int k  = idx / (BN / 4);
            int nq = idx % (BN / 4);
            *(float4*)&Bs[k][nq * 4] =
                *(const float4*)&B[(size_t)(k0 + k) * N + col0 + nq * 4];
        }
        __syncthreads();

#pragma unroll
        for (int k = 0; k < BK; k++) {
            float ra[TM], rb[TN];
#pragma unroll
            for (int i = 0; i < TM; i++) ra[i] = As[k][ty * TM + i];
#pragma unroll
            for (int j = 0; j < TN; j++) rb[j] = Bs[k][tx * TN + j];
#pragma unroll
            for (int i = 0; i < TM; i++)
#pragma unroll
                for (int j = 0; j < TN; j++) acc[i][j] += ra[i] * rb[j];
        }
        __syncthreads();
    }

#pragma unroll
    for (int i = 0; i < TM; i++) {
        int m = row0 + ty * TM + i;
        if (m < M) {
#pragma unroll
            for (int j = 0; j < TN; j += 4) {
                float4 v = make_float4(acc[i][j], acc[i][j + 1], acc[i][j + 2], acc[i][j + 3]);
                *(float4*)&C[(size_t)m * N + col0 + tx * TN + j] = v;
            }
        }
    }
}

// ---------------- gather-based segment mean (+bias, +relu) --------------------
// F4 float4 lanes per segment row; dst[seg] = (1/deg) * sum_{r in adj[seg]} src[r]
template <int F4, bool RELU, bool BIAS>
__global__ void agg_k(const float4* __restrict__ src, const int* __restrict__ rp,
                      const int* __restrict__ adj, const float* __restrict__ bias,
                      float4* __restrict__ dst, int nseg) {
    const int spb  = blockDim.x / F4;
    const int seg  = blockIdx.x * spb + threadIdx.x / F4;
    const int lane = threadIdx.x % F4;
    if (seg >= nseg) return;
    int s = rp[seg], e = rp[seg + 1];
    float4 acc = make_float4(0.f, 0.f, 0.f, 0.f);
    for (int j = s; j < e; j++) {
        int r    = __ldg(&adj[j]);
        float4 v = src[(size_t)r * F4 + lane];
        acc.x += v.x; acc.y += v.y; acc.z += v.z; acc.w += v.w;
    }
    float inv = (e > s) ? 1.0f / (float)(e - s) : 0.0f;
    acc.x *= inv; acc.y *= inv; acc.z *= inv; acc.w *= inv;
    if (BIAS) {
        float4 b = ((const float4*)bias)[lane];
        acc.x += b.x; acc.y += b.y; acc.z += b.z; acc.w += b.w;
    }
    if (RELU) {
        acc.x = fmaxf(acc.x, 0.f); acc.y = fmaxf(acc.y, 0.f);
        acc.z = fmaxf(acc.z, 0.f); acc.w = fmaxf(acc.w, 0.f);
    }
    dst[(size_t)seg * F4 + lane] = acc;
}

// ---------------- in-place log_softmax over 64 channels (warp per row) --------
__global__ void logsm64(float* __restrict__ d, int n) {
    int row  = blockIdx.x * (blockDim.x / 32) + threadIdx.x / 32;
    int lane = threadIdx.x & 31;
    if (row >= n) return;
    float2 v = *(float2*)&d[(size_t)row * 64 + lane * 2];
    float mx = fmaxf(v.x, v.y);
#pragma unroll
    for (int o = 16; o > 0; o >>= 1) mx = fmaxf(mx, __shfl_xor_sync(0xffffffffu, mx, o));
    float s = __expf(v.x - mx) + __expf(v.y - mx);
#pragma unroll
    for (int o = 16; o > 0; o >>= 1) s += __shfl_xor_sync(0xffffffffu, s, o);
    float l = mx + __logf(s);
    v.x -= l; v.y -= l;
    *(float2*)&d[(size_t)row * 64 + lane * 2] = v;
}

// ---------------- launch ------------------------------------------------------
extern "C" void kernel_launch(void* const* d_in, const int* in_sizes, int n_in,
                              void* d_out, int out_size) {
    const float* x   = (const float*)d_in[0];
    const int*   ei  = (const int*)d_in[1];     // int32 view; dtype auto-detected
    const float* W1  = (const float*)d_in[2];
    const float* b1  = (const float*)d_in[3];
    const float* W2  = (const float*)d_in[4];
    const float* b2  = (const float*)d_in[5];
    float*       out = (float*)d_out;

    float *h1, *m1, *h2, *m2;
    int *degN, *degE, *rpN, *rpE, *adjE, *adjN;
    cudaGetSymbolAddress((void**)&h1,   g_h1);
    cudaGetSymbolAddress((void**)&m1,   g_m1);
    cudaGetSymbolAddress((void**)&h2,   g_h2);
    cudaGetSymbolAddress((void**)&m2,   g_m2);
    cudaGetSymbolAddress((void**)&degN, g_degN);
    cudaGetSymbolAddress((void**)&degE, g_degE);
    cudaGetSymbolAddress((void**)&rpN,  g_rpN);
    cudaGetSymbolAddress((void**)&rpE,  g_rpE);
    cudaGetSymbolAddress((void**)&adjE, g_adjE);
    cudaGetSymbolAddress((void**)&adjN, g_adjN);

    // dtype detect + CSR build
    detect_dtype<<<1, 256>>>(ei);
    zero_counts<<<(NN + 255) / 256, 256>>>();
    count_deg<<<(NNZT + 255) / 256, 256>>>(ei);
    scan_excl<<<1, 1024>>>(degN, rpN, NN);
    scan_excl<<<1, 1024>>>(degE, rpE, NE);
    fill_adj<<<(NNZT + 255) / 256, 256>>>(ei);

    // conv1: h1 = x @ W1
    sgemm_k<128, 128, 8, 8, 8>
        <<<dim3((NN + 127) / 128, HIDC / 128), 256>>>(x, W1, h1, NN, HIDC, INC);
    // node -> hyperedge (mean), conv1
    agg_k<HIDC / 4, false, false>
        <<<(NE * (HIDC / 4) + 255) / 256, 256>>>((const float4*)h1, rpE, adjE, nullptr,
                                                 (float4*)m1, NE);
    // hyperedge -> node (mean) + b1 + relu, conv1 (writes back into h1)
    agg_k<HIDC / 4, true, true>
        <<<(NN * (HIDC / 4) + 255) / 256, 256>>>((const float4*)m1, rpN, adjN, b1,
                                                 (float4*)h1, NN);

    // conv2: h2 = h1 @ W2
    sgemm_k<128, 64, 8, 8, 4>
        <<<dim3((NN + 127) / 128, OUTC / 64), 256>>>(h1, W2, h2, NN, OUTC, HIDC);
    // node -> hyperedge (mean), conv2
    agg_k<OUTC / 4, false, false>
        <<<(NE * (OUTC / 4) + 255) / 256, 256>>>((const float4*)h2, rpE, adjE, nullptr,
                                                 (float4*)m2, NE);
    // hyperedge -> node (mean) + b2, conv2 -> d_out
    agg_k<OUTC / 4, false, true>
        <<<(NN * (OUTC / 4) + 255) / 256, 256>>>((const float4*)m2, rpN, adjN, b2,
                                                 (float4*)out, NN);

    // log_softmax in place
    logsm64<<<(NN + 7) / 8, 256>>>(out, NN);
}

// round 8
// speedup vs baseline: 1.0047x; 1.0029x over previous
#include <cuda_runtime.h>

#define NN   50000
#define NE   50000
#define NNZT 800000
#define INC  512
#define HIDC 256
#define OUTC 64

// ---------------- scratch (static device globals; no allocs allowed) ----------
__device__ float g_h1[NN * HIDC];   // x@W1, later reused for relu(conv1) output
__device__ float g_m1[NE * HIDC];   // hyperedge features, conv1
__device__ float g_h2[NN * OUTC];   // h@W2
__device__ float g_m2[NE * OUTC];   // hyperedge features, conv2
__device__ int   g_degN[NN];
__device__ int   g_degE[NE];
__device__ int   g_rpN[NN + 1];
__device__ int   g_rpE[NE + 1];
__device__ int   g_curN[NN];
__device__ int   g_curE[NE];
__device__ int   g_adjE[NNZT];      // node ids grouped by hyperedge
__device__ int   g_adjN[NNZT];      // hyperedge ids grouped by node
__device__ int   g_is64;            // 1 if edge_index buffer is int64, 0 if int32

// ---------------- dtype detection -------------------------------------------
// int64 non-negative values < 2^31 (little-endian): every odd int32 word is 0.
// Genuine int32 indices: odd words are random in [0, 50000) -> ~never all zero.
__global__ void detect_dtype(const int* __restrict__ ei32) {
    __shared__ int any_nonzero;
    if (threadIdx.x == 0) any_nonzero = 0;
    __syncthreads();
    int t = threadIdx.x;
    for (int j = t; j < 1024; j += blockDim.x) {
        if (ei32[2 * j + 1] != 0) atomicOr(&any_nonzero, 1);
    }
    __syncthreads();
    if (threadIdx.x == 0) g_is64 = any_nonzero ? 0 : 1;
}

__device__ __forceinline__ void load_pair(const int* __restrict__ ei32, int i,
                                          int& v, int& e) {
    if (g_is64) {
        v = ei32[2 * (size_t)i];
        e = ei32[2 * ((size_t)NNZT + i)];
    } else {
        v = ei32[i];
        e = ei32[NNZT + i];
    }
}

// ---------------- CSR build ---------------------------------------------------
__global__ void zero_counts() {
    int i = blockIdx.x * blockDim.x + threadIdx.x;
    if (i < NN) { g_degN[i] = 0; g_curN[i] = 0; }
    if (i < NE) { g_degE[i] = 0; g_curE[i] = 0; }
}

__global__ void count_deg(const int* __restrict__ ei32) {
    int i = blockIdx.x * blockDim.x + threadIdx.x;
    if (i >= NNZT) return;
    int v, e;
    load_pair(ei32, i, v, e);
    if ((unsigned)v >= NN || (unsigned)e >= NE) return;  // safety net
    atomicAdd(&g_degN[v], 1);
    atomicAdd(&g_degE[e], 1);
}

// exclusive scan of n (<=50000) ints, single block of 1024 threads
__global__ void scan_excl(const int* __restrict__ deg, int* __restrict__ rp, int n) {
    __shared__ int sh[1024];
    __shared__ int soff;
    int t = threadIdx.x;
    if (t == 0) soff = 0;
    __syncthreads();
    for (int base = 0; base < n; base += 1024) {
        int i = base + t;
        int v = (i < n) ? deg[i] : 0;
        sh[t] = v;
        __syncthreads();
        for (int d = 1; d < 1024; d <<= 1) {
            int add = (t >= d) ? sh[t - d] : 0;
            __syncthreads();
            sh[t] += add;
            __syncthreads();
        }
        if (i < n) rp[i] = soff + sh[t] - v;
        int tot = sh[1023];
        __syncthreads();
        if (t == 0) soff += tot;
        __syncthreads();
    }
    if (t == 0) rp[n] = soff;
}

__global__ void fill_adj(const int* __restrict__ ei32) {
    int i = blockIdx.x * blockDim.x + threadIdx.x;
    if (i >= NNZT) return;
    int v, e;
    load_pair(ei32, i, v, e);
    if ((unsigned)v >= NN || (unsigned)e >= NE) return;  // safety net
    int p = atomicAdd(&g_curE[e], 1);
    g_adjE[g_rpE[e] + p] = v;
    int q = atomicAdd(&g_curN[v], 1);
    g_adjN[g_rpN[v] + q] = e;
}

// ---------------- tiled SGEMM: C[M,N] = A[M,K] @ B[K,N] -----------------------
template <int BM, int BN, int BK, int TM, int TN>
__global__ void sgemm_k(const float* __restrict__ A, const float* __restrict__ B,
                        float* __restrict__ C, int M, int N, int K) {
    constexpr int NT = (BM / TM) * (BN / TN);
    __shared__ float As[BK][BM];
    __shared__ float Bs[BK][BN];
    const int tid  = threadIdx.x;
    const int tx   = tid % (BN / TN);
    const int ty   = tid / (BN / TN);
    const int row0 = blockIdx.x * BM;
    const int col0 = blockIdx.y * BN;

    float acc[TM][TN] = {};

    for (int k0 = 0; k0 < K; k0 += BK) {
        for (int idx = tid; idx < BM * BK / 4; idx += NT) {
            int m  = idx / (BK / 4);
            int kq = idx % (BK / 4);
            float4 a = make_float4(0.f, 0.f, 0.f, 0.f);
            if (row0 + m < M)
                a = *(const float4*)&A[(size_t)(row0 + m) * K + k0 + kq * 4];
            As[kq * 4 + 0][m] = a.x;
            As[kq * 4 + 1][m] = a.y;
            As[kq * 4 + 2][m] = a.z;
            As[kq * 4 + 3][m] = a.w;
        }
        for (int idx = tid; idx < BK * BN / 4; idx += NT) {
            int k  = idx / (BN / 4);
            int nq = idx % (BN / 4);
            *(float4*)&Bs[k][nq * 4] =
                *(const float4*)&B[(size_t)(k0 + k) * N + col0 + nq * 4];
        }
        __syncthreads();

#pragma unroll
        for (int k = 0; k < BK; k++) {
            float ra[TM], rb[TN];
#pragma unroll
            for (int i = 0; i < TM; i++) ra[i] = As[k][ty * TM + i];
#pragma unroll
            for (int j = 0; j < TN; j++) rb[j] = Bs[k][tx * TN + j];
#pragma unroll
            for (int i = 0; i < TM; i++)
#pragma unroll
                for (int j = 0; j < TN; j++) acc[i][j] += ra[i] * rb[j];
        }
        __syncthreads();
    }

#pragma unroll
    for (int i = 0; i < TM; i++) {
        int m = row0 + ty * TM + i;
        if (m < M) {
#pragma unroll
            for (int j = 0; j < TN; j += 4) {
                float4 v = make_float4(acc[i][j], acc[i][j + 1], acc[i][j + 2], acc[i][j + 3]);
                *(float4*)&C[(size_t)m * N + col0 + tx * TN + j] = v;
            }
        }
    }
}

// ---------------- gather-based segment mean (+bias, +relu) --------------------
// F4 float4 lanes per segment row; dst[seg] = (1/deg) * sum_{r in adj[seg]} src[r]
template <int F4, bool RELU, bool BIAS>
__global__ void agg_k(const float4* __restrict__ src, const int* __restrict__ rp,
                      const int* __restrict__ adj, const float* __restrict__ bias,
                      float4* __restrict__ dst, int nseg) {
    const int spb  = blockDim.x / F4;
    const int seg  = blockIdx.x * spb + threadIdx.x / F4;
    const int lane = threadIdx.x % F4;
    if (seg >= nseg) return;
    int s = rp[seg], e = rp[seg + 1];
    float4 acc = make_float4(0.f, 0.f, 0.f, 0.f);
    for (int j = s; j < e; j++) {
        int r    = __ldg(&adj[j]);
        float4 v = src[(size_t)r * F4 + lane];
        acc.x += v.x; acc.y += v.y; acc.z += v.z; acc.w += v.w;
    }
    float inv = (e > s) ? 1.0f / (float)(e - s) : 0.0f;
    acc.x *= inv; acc.y *= inv; acc.z *= inv; acc.w *= inv;
    if (BIAS) {
        float4 b = ((const float4*)bias)[lane];
        acc.x += b.x; acc.y += b.y; acc.z += b.z; acc.w += b.w;
    }
    if (RELU) {
        acc.x = fmaxf(acc.x, 0.f); acc.y = fmaxf(acc.y, 0.f);
        acc.z = fmaxf(acc.z, 0.f); acc.w = fmaxf(acc.w, 0.f);
    }
    dst[(size_t)seg * F4 + lane] = acc;
}

// ---------------- in-place log_softmax over 64 channels (warp per row) --------
__global__ void logsm64(float* __restrict__ d, int n) {
    int row  = blockIdx.x * (blockDim.x / 32) + threadIdx.x / 32;
    int lane = threadIdx.x & 31;
    if (row >= n) return;
    float2 v = *(float2*)&d[(size_t)row * 64 + lane * 2];
    float mx = fmaxf(v.x, v.y);
#pragma unroll
    for (int o = 16; o > 0; o >>= 1) mx = fmaxf(mx, __shfl_xor_sync(0xffffffffu, mx, o));
    float s = __expf(v.x - mx) + __expf(v.y - mx);
#pragma unroll
    for (int o = 16; o > 0; o >>= 1) s += __shfl_xor_sync(0xffffffffu, s, o);
    float l = mx + __logf(s);
    v.x -= l; v.y -= l;
    *(float2*)&d[(size_t)row * 64 + lane * 2] = v;
}

// ---------------- launch ------------------------------------------------------
extern "C" void kernel_launch(void* const* d_in, const int* in_sizes, int n_in,
                              void* d_out, int out_size) {
    const float* x   = (const float*)d_in[0];
    const int*   ei  = (const int*)d_in[1];     // int32 view; dtype auto-detected
    const float* W1  = (const float*)d_in[2];
    const float* b1  = (const float*)d_in[3];
    const float* W2  = (const float*)d_in[4];
    const float* b2  = (const float*)d_in[5];
    float*       out = (float*)d_out;

    float *h1, *m1, *h2, *m2;
    int *degN, *degE, *rpN, *rpE, *adjE, *adjN;
    cudaGetSymbolAddress((void**)&h1,   g_h1);
    cudaGetSymbolAddress((void**)&m1,   g_m1);
    cudaGetSymbolAddress((void**)&h2,   g_h2);
    cudaGetSymbolAddress((void**)&m2,   g_m2);
    cudaGetSymbolAddress((void**)&degN, g_degN);
    cudaGetSymbolAddress((void**)&degE, g_degE);
    cudaGetSymbolAddress((void**)&rpN,  g_rpN);
    cudaGetSymbolAddress((void**)&rpE,  g_rpE);
    cudaGetSymbolAddress((void**)&adjE, g_adjE);
    cudaGetSymbolAddress((void**)&adjN, g_adjN);

    // dtype detect + CSR build
    detect_dtype<<<1, 256>>>(ei);
    zero_counts<<<(NN + 255) / 256, 256>>>();
    count_deg<<<(NNZT + 255) / 256, 256>>>(ei);
    scan_excl<<<1, 1024>>>(degN, rpN, NN);
    scan_excl<<<1, 1024>>>(degE, rpE, NE);
    fill_adj<<<(NNZT + 255) / 256, 256>>>(ei);

    // conv1: h1 = x @ W1
    sgemm_k<128, 128, 8, 8, 8>
        <<<dim3((NN + 127) / 128, HIDC / 128), 256>>>(x, W1, h1, NN, HIDC, INC);
    // node -> hyperedge (mean), conv1
    agg_k<HIDC / 4, false, false>
        <<<(NE * (HIDC / 4) + 255) / 256, 256>>>((const float4*)h1, rpE, adjE, nullptr,
                                                 (float4*)m1, NE);
    // hyperedge -> node (mean) + b1 + relu, conv1 (writes back into h1)
    agg_k<HIDC / 4, true, true>
        <<<(NN * (HIDC / 4) + 255) / 256, 256>>>((const float4*)m1, rpN, adjN, b1,
                                                 (float4*)h1, NN);

    // conv2: h2 = h1 @ W2
    sgemm_k<128, 64, 8, 8, 4>
        <<<dim3((NN + 127) / 128, OUTC / 64), 256>>>(h1, W2, h2, NN, OUTC, HIDC);
    // node -> hyperedge (mean), conv2
    agg_k<OUTC / 4, false, false>
        <<<(NE * (OUTC / 4) + 255) / 256, 256>>>((const float4*)h2, rpE, adjE, nullptr,
                                                 (float4*)m2, NE);
    // hyperedge -> node (mean) + b2, conv2 -> d_out
    agg_k<OUTC / 4, false, true>
        <<<(NN * (OUTC / 4) + 255) / 256, 256>>>((const float4*)m2, rpN, adjN, b2,
                                                 (float4*)out, NN);

    // log_softmax in place
    logsm64<<<(NN + 7) / 8, 256>>>(out, NN);
}